// round 6
// baseline (speedup 1.0000x reference)
#include <cuda_runtime.h>
#include <cuda_bf16.h>

#define NPTS   65536
#define CHN    256
#define BATCH  16
#define LOUT   8192
#define LOG2L  13

// g_off[b] = first index with batch id >= b; g_off[BATCH] = NPTS.
__device__ int g_off[BATCH + 1];

// ------------------------------------------------------- boundary detect ---
// batch sorted; int4 loads, boundary write-out, no atomics.
__global__ void boundary_kernel(const int* __restrict__ batch) {
    int t = blockIdx.x * blockDim.x + threadIdx.x;   // 0 .. NPTS/4-1
    if (t >= NPTS / 4) return;
    int4 v = ((const int4*)batch)[t];
    int prev = (t == 0) ? -1 : __ldg(&batch[4 * t - 1]);
    for (int bb = prev + 1; bb <= v.x; bb++) g_off[bb] = 4 * t + 0;
    for (int bb = v.x + 1;  bb <= v.y; bb++) g_off[bb] = 4 * t + 1;
    for (int bb = v.y + 1;  bb <= v.z; bb++) g_off[bb] = 4 * t + 2;
    for (int bb = v.z + 1;  bb <= v.w; bb++) g_off[bb] = 4 * t + 3;
    if (t == NPTS / 4 - 1)
        for (int bb = v.w + 1; bb <= BATCH; bb++) g_off[bb] = NPTS;
}

// ----------------------------------------------------------- main gather ---
// blocks [0, PT_BLOCKS)              : points gather.
// blocks [PT_BLOCKS, PT_BLOCKS+8192) : feature gather-transpose, registers only.
//
// L1-wavefront-optimized lane mapping:
//   lane = jq_l*8 + c4_l   (warp = 4 j-quads x 8 channel-quads)
//   LDG.128: 8-lane groups read 128B contiguous of one row -> 4 lines/instr.
//   STG.128: 8 channel-groups x 4 lanes x 16B = 64B contiguous -> 8 lines/instr.
//   48 wf per warp per 2KB output (vs 144 with jq-only lanes).
#define PT_BLOCKS 128

__global__ __launch_bounds__(256)
void gather_kernel(const float* __restrict__ px,
                   const float4* __restrict__ feat4,
                   float* __restrict__ out_point,
                   float* __restrict__ out_feat) {
    __shared__ int s_off, s_cnt;
    int bid = blockIdx.x;
    int tid = threadIdx.x;

    if (bid < PT_BLOCKS) {
        int idx = bid * 256 + tid;            // 0..32767
        int b = idx >> 11;
        if (tid == 0) { s_off = g_off[b]; s_cnt = g_off[b + 1] - g_off[b]; }
        __syncthreads();
        int off = s_off, cnt = s_cnt;
        int j = (idx & 2047) * 4;
        float4 ox, oy, oz;
        #pragma unroll
        for (int t = 0; t < 4; t++) {
            int src = off + (int)(((unsigned)((j + t) * cnt)) >> LOG2L);
            const float* p = px + 3 * src;
            ((float*)&ox)[t] = p[0];
            ((float*)&oy)[t] = p[1];
            ((float*)&oz)[t] = p[2];
        }
        size_t base = (size_t)b * 3 * LOUT + j;
        __stcs((float4*)(out_point + base),            ox);
        __stcs((float4*)(out_point + base + LOUT),     oy);
        __stcs((float4*)(out_point + base + 2 * LOUT), oz);
        return;
    }

    // ---- features ----
    int bid_f = bid - PT_BLOCKS;              // 0..8191
    int b   = bid_f >> 9;                     // 16 batches
    int jqg = bid_f & 511;                    // 4 j-quads per block
    if (tid == 0) { s_off = g_off[b]; s_cnt = g_off[b + 1] - g_off[b]; }
    __syncthreads();
    int off = s_off, cnt = s_cnt;

    int warp = tid >> 5, lane = tid & 31;
    int jq = jqg * 4 + (lane >> 3);           // 0..2047
    int c4 = warp * 8 + (lane & 7);           // 0..63
    int j0 = jq * 4;

    float4 v0 = __ldg(feat4 + (size_t)(off + (int)(((unsigned)((j0 + 0) * cnt)) >> LOG2L)) * (CHN / 4) + c4);
    float4 v1 = __ldg(feat4 + (size_t)(off + (int)(((unsigned)((j0 + 1) * cnt)) >> LOG2L)) * (CHN / 4) + c4);
    float4 v2 = __ldg(feat4 + (size_t)(off + (int)(((unsigned)((j0 + 2) * cnt)) >> LOG2L)) * (CHN / 4) + c4);
    float4 v3 = __ldg(feat4 + (size_t)(off + (int)(((unsigned)((j0 + 3) * cnt)) >> LOG2L)) * (CHN / 4) + c4);

    // 4x4 register transpose + float4 stores (channels 4c4..4c4+3, j0..j0+3).
    float* ob = out_feat + ((size_t)b * CHN + 4 * c4) * LOUT + j0;
    float4 o;
    o.x = v0.x; o.y = v1.x; o.z = v2.x; o.w = v3.x;
    __stcs((float4*)(ob + 0 * LOUT), o);
    o.x = v0.y; o.y = v1.y; o.z = v2.y; o.w = v3.y;
    __stcs((float4*)(ob + 1 * LOUT), o);
    o.x = v0.z; o.y = v1.z; o.z = v2.z; o.w = v3.z;
    __stcs((float4*)(ob + 2 * LOUT), o);
    o.x = v0.w; o.y = v1.w; o.z = v2.w; o.w = v3.w;
    __stcs((float4*)(ob + 3 * LOUT), o);
}

// ------------------------------------------------------------- launch ------
extern "C" void kernel_launch(void* const* d_in, const int* in_sizes, int n_in,
                              void* d_out, int out_size) {
    const float* points_x = (const float*)d_in[0];   // [N,3]
    const float* feat     = (const float*)d_in[1];   // [N,C]
    const int*   batch    = (const int*)d_in[2];     // [N]

    float* out_point = (float*)d_out;                              // [B,3,L]
    float* out_feat  = (float*)d_out + (size_t)BATCH * 3 * LOUT;   // [B,C,L]

    boundary_kernel<<<64, 256>>>(batch);

    int nblocks = PT_BLOCKS + 8192;
    gather_kernel<<<nblocks, 256>>>(points_x, (const float4*)feat,
                                    out_point, out_feat);
}